// round 2
// baseline (speedup 1.0000x reference)
#include <cuda_runtime.h>
#include <cuda_bf16.h>
#include <math.h>

// ---------------------------------------------------------------------------
// Problem constants
// ---------------------------------------------------------------------------
#define BATCH   4
#define TSEQ    2048
#define CEMB    1024
#define NHEAD   16
#define HDIM    64
#define C3      (3*CEMB)      // 3072
#define CFF     (4*CEMB)      // 4096
#define NROWS   (BATCH*TSEQ)  // 8192
#define LN_EPS  1e-5f

// ---------------------------------------------------------------------------
// Scratch (alloc-free rule: __device__ globals)
// ---------------------------------------------------------------------------
__device__ float g_qkv[(size_t)NROWS * C3];    // 100 MB
__device__ float g_att[(size_t)NROWS * CEMB];  // 33.5 MB
__device__ float g_xn [(size_t)NROWS * CEMB];  // 33.5 MB (post-ln1 activations)
__device__ float g_h  [(size_t)NROWS * CFF];   // 134 MB
__device__ float g_mlp[(size_t)NROWS * CEMB];  // 33.5 MB

// ---------------------------------------------------------------------------
// SGEMM: C = A[MxK] @ B[KxN] + bias (optional exact GeLU)
// 128x128 tile, BK=8, 256 threads, 8x8 microtile
// Requires M%128==0, N%128==0, K%8==0 (true for all three GEMMs here)
// ---------------------------------------------------------------------------
template<bool GELU>
__global__ __launch_bounds__(256)
void sgemm_bias_kernel(const float* __restrict__ A, const float* __restrict__ B,
                       const float* __restrict__ bias, float* __restrict__ C,
                       int M, int N, int K)
{
    __shared__ float As[8][128];
    __shared__ float Bs[8][128];

    const int t  = threadIdx.x;
    const int tx = t & 15;        // 0..15
    const int ty = t >> 4;        // 0..15
    const int row0 = blockIdx.y * 128;
    const int col0 = blockIdx.x * 128;

    // A loader: each thread one float4; row = t/2 (0..127), k4 = (t%2)*4
    const int aRow = t >> 1;
    const int aK4  = (t & 1) * 4;
    // B loader: row = t/32 (0..7), col4 = (t%32)*4
    const int bRow = t >> 5;
    const int bCol = (t & 31) * 4;

    const float* Aptr = A + (size_t)(row0 + aRow) * K + aK4;
    const float* Bptr = B + (size_t)bRow * N + col0 + bCol;

    float acc[8][8];
    #pragma unroll
    for (int i = 0; i < 8; i++)
        #pragma unroll
        for (int j = 0; j < 8; j++)
            acc[i][j] = 0.f;

    for (int kk = 0; kk < K; kk += 8) {
        float4 av = *(const float4*)(Aptr + kk);
        As[aK4+0][aRow] = av.x;
        As[aK4+1][aRow] = av.y;
        As[aK4+2][aRow] = av.z;
        As[aK4+3][aRow] = av.w;
        *(float4*)&Bs[bRow][bCol] = *(const float4*)(Bptr + (size_t)kk * N);
        __syncthreads();

        #pragma unroll
        for (int k = 0; k < 8; k++) {
            float4 a0 = *(const float4*)&As[k][ty*8];
            float4 a1 = *(const float4*)&As[k][ty*8+4];
            float4 b0 = *(const float4*)&Bs[k][tx*8];
            float4 b1 = *(const float4*)&Bs[k][tx*8+4];
            float ra[8] = {a0.x,a0.y,a0.z,a0.w,a1.x,a1.y,a1.z,a1.w};
            float rb[8] = {b0.x,b0.y,b0.z,b0.w,b1.x,b1.y,b1.z,b1.w};
            #pragma unroll
            for (int i = 0; i < 8; i++)
                #pragma unroll
                for (int j = 0; j < 8; j++)
                    acc[i][j] = fmaf(ra[i], rb[j], acc[i][j]);
        }
        __syncthreads();
    }

    // epilogue
    #pragma unroll
    for (int i = 0; i < 8; i++) {
        int r = row0 + ty*8 + i;
        #pragma unroll
        for (int j = 0; j < 8; j++) {
            int c = col0 + tx*8 + j;
            float v = acc[i][j] + bias[c];
            if (GELU) {
                v = 0.5f * v * (1.f + erff(v * 0.70710678118654752f));
            }
            C[(size_t)r * N + c] = v;
        }
    }
}

// ---------------------------------------------------------------------------
// Flash attention (causal), fp32. BM=BN=64. 256 threads.
// Thread t -> row i = t/4, col-group cg = t%4 (16 cols each).
// qkv layout per row (3072): [q(16 heads x 64) | k | v]
// ---------------------------------------------------------------------------
#define ATT_P 68   // padded row stride (floats), 16B-aligned, bank-staggered
#define ATT_SMEM (4 * 64 * ATT_P * 4)  // Qs,Ks,Vs,Ss = 69632 bytes

__global__ __launch_bounds__(256)
void flash_attn_kernel(const float* __restrict__ qkv, float* __restrict__ y)
{
    extern __shared__ float sm[];
    float* Qs = sm;                 // [64][ATT_P]
    float* Ks = sm + 64*ATT_P;
    float* Vs = sm + 128*ATT_P;
    float* Ss = sm + 192*ATT_P;

    const int qt = blockIdx.x;            // q tile 0..31
    const int bh = blockIdx.y;            // 0..63
    const int b  = bh >> 4;
    const int h  = bh & 15;
    const int t  = threadIdx.x;
    const int i  = t >> 2;                // row in tile 0..63
    const int cg = t & 3;
    const int c0 = cg << 4;
    const int qs = qt * 64;

    const size_t base = (size_t)(b * TSEQ) * C3 + h * HDIM;

    // load Q tile (coalesced, each thread 4 float4s)
    {
        const int d4 = (t & 15) * 4;
        const int r0 = t >> 4;
        #pragma unroll
        for (int rr = 0; rr < 64; rr += 16) {
            int row = r0 + rr;
            *(float4*)&Qs[row*ATT_P + d4] =
                *(const float4*)(qkv + base + (size_t)(qs + row) * C3 + d4);
        }
    }

    float m = -INFINITY, l = 0.f;
    float O[16];
    #pragma unroll
    for (int j = 0; j < 16; j++) O[j] = 0.f;

    for (int kt = 0; kt <= qt; kt++) {
        const int ks = kt * 64;
        __syncthreads();   // protect Ks/Vs/Ss from previous iteration's readers
        {
            const int d4 = (t & 15) * 4;
            const int r0 = t >> 4;
            #pragma unroll
            for (int rr = 0; rr < 64; rr += 16) {
                int row = r0 + rr;
                const float* kp = qkv + base + (size_t)(ks + row) * C3 + CEMB + d4;
                *(float4*)&Ks[row*ATT_P + d4] = *(const float4*)kp;
                *(float4*)&Vs[row*ATT_P + d4] = *(const float4*)(kp + CEMB);
            }
        }
        __syncthreads();

        // S = (Q K^T) * 1/8, causal-masked on the diagonal tile
        float acc[16];
        #pragma unroll
        for (int jj = 0; jj < 16; jj++) acc[jj] = 0.f;
        #pragma unroll 4
        for (int d4 = 0; d4 < 64; d4 += 4) {
            float4 qv = *(const float4*)&Qs[i*ATT_P + d4];
            #pragma unroll
            for (int jj = 0; jj < 16; jj++) {
                float4 kv = *(const float4*)&Ks[(c0+jj)*ATT_P + d4];
                acc[jj] += qv.x*kv.x + qv.y*kv.y + qv.z*kv.z + qv.w*kv.w;
            }
        }

        const bool diag = (kt == qt);
        float mt = -INFINITY;
        #pragma unroll
        for (int jj = 0; jj < 16; jj++) {
            float s = acc[jj] * 0.125f;
            if (diag && (c0 + jj) > i) s = -INFINITY;
            acc[jj] = s;
            mt = fmaxf(mt, s);
        }
        mt = fmaxf(mt, __shfl_xor_sync(0xffffffffu, mt, 1));
        mt = fmaxf(mt, __shfl_xor_sync(0xffffffffu, mt, 2));
        const float mnew = fmaxf(m, mt);

        float lt = 0.f;
        #pragma unroll
        for (int jj = 0; jj < 16; jj++) {
            float p = expf(acc[jj] - mnew);
            Ss[i*ATT_P + c0 + jj] = p;
            lt += p;
        }
        lt += __shfl_xor_sync(0xffffffffu, lt, 1);
        lt += __shfl_xor_sync(0xffffffffu, lt, 2);

        const float scale = expf(m - mnew);
        m = mnew;
        l = l * scale + lt;
        #pragma unroll
        for (int cc = 0; cc < 16; cc++) O[cc] *= scale;
        __syncthreads();   // Ss fully written

        // O += P @ V
        for (int j = 0; j < 64; j++) {
            float p = Ss[i*ATT_P + j];
            const float* vrow = &Vs[j*ATT_P + c0];
            #pragma unroll
            for (int cc4 = 0; cc4 < 16; cc4 += 4) {
                float4 vv = *(const float4*)(vrow + cc4);
                O[cc4+0] = fmaf(p, vv.x, O[cc4+0]);
                O[cc4+1] = fmaf(p, vv.y, O[cc4+1]);
                O[cc4+2] = fmaf(p, vv.z, O[cc4+2]);
                O[cc4+3] = fmaf(p, vv.w, O[cc4+3]);
            }
        }
    }

    const float inv = 1.f / l;
    float* dst = y + (size_t)(b * TSEQ + qs + i) * CEMB + h * HDIM + c0;
    #pragma unroll
    for (int cc = 0; cc < 16; cc++) dst[cc] = O[cc] * inv;
}

// ---------------------------------------------------------------------------
// Fused residual-add + LayerNorm: out = LN(a + r) * g + b ; one block per row
// ---------------------------------------------------------------------------
__global__ __launch_bounds__(256)
void add_ln_kernel(const float* __restrict__ a, const float* __restrict__ r,
                   const float* __restrict__ gam, const float* __restrict__ bet,
                   float* __restrict__ out)
{
    const int row = blockIdx.x;
    const int t   = threadIdx.x;

    float4 va = ((const float4*)(a + (size_t)row * CEMB))[t];
    float4 vr = ((const float4*)(r + (size_t)row * CEMB))[t];
    float4 v;
    v.x = va.x + vr.x; v.y = va.y + vr.y; v.z = va.z + vr.z; v.w = va.w + vr.w;

    float s  = v.x + v.y + v.z + v.w;
    float sq = v.x*v.x + v.y*v.y + v.z*v.z + v.w*v.w;
    #pragma unroll
    for (int o = 16; o; o >>= 1) {
        s  += __shfl_xor_sync(0xffffffffu, s,  o);
        sq += __shfl_xor_sync(0xffffffffu, sq, o);
    }
    __shared__ float ps[8], pq[8];
    const int w = t >> 5, lane = t & 31;
    if (lane == 0) { ps[w] = s; pq[w] = sq; }
    __syncthreads();
    s = 0.f; sq = 0.f;
    #pragma unroll
    for (int k = 0; k < 8; k++) { s += ps[k]; sq += pq[k]; }

    const float mu   = s * (1.f / CEMB);
    const float var  = sq * (1.f / CEMB) - mu * mu;
    const float rstd = rsqrtf(var + LN_EPS);

    float4 gg = ((const float4*)gam)[t];
    float4 bb = ((const float4*)bet)[t];
    float4 o;
    o.x = (v.x - mu) * rstd * gg.x + bb.x;
    o.y = (v.y - mu) * rstd * gg.y + bb.y;
    o.z = (v.z - mu) * rstd * gg.z + bb.z;
    o.w = (v.w - mu) * rstd * gg.w + bb.w;
    ((float4*)(out + (size_t)row * CEMB))[t] = o;
}

// ---------------------------------------------------------------------------
// Launch
// ---------------------------------------------------------------------------
extern "C" void kernel_launch(void* const* d_in, const int* in_sizes, int n_in,
                              void* d_out, int out_size)
{
    const float* x     = (const float*)d_in[0];
    const float* w_qkv = (const float*)d_in[1];
    const float* b_qkv = (const float*)d_in[2];
    const float* ln1_g = (const float*)d_in[3];
    const float* ln1_b = (const float*)d_in[4];
    const float* w_fc1 = (const float*)d_in[5];
    const float* b_fc1 = (const float*)d_in[6];
    const float* w_fc2 = (const float*)d_in[7];
    const float* b_fc2 = (const float*)d_in[8];
    const float* ln2_g = (const float*)d_in[9];
    const float* ln2_b = (const float*)d_in[10];
    float* out = (float*)d_out;

    void *p_qkv, *p_att, *p_xn, *p_h, *p_mlp;
    cudaGetSymbolAddress(&p_qkv, g_qkv);
    cudaGetSymbolAddress(&p_att, g_att);
    cudaGetSymbolAddress(&p_xn,  g_xn);
    cudaGetSymbolAddress(&p_h,   g_h);
    cudaGetSymbolAddress(&p_mlp, g_mlp);
    float* qkv = (float*)p_qkv;
    float* att = (float*)p_att;
    float* xn  = (float*)p_xn;
    float* hbuf= (float*)p_h;
    float* mlp = (float*)p_mlp;

    cudaFuncSetAttribute(flash_attn_kernel,
                         cudaFuncAttributeMaxDynamicSharedMemorySize, ATT_SMEM);

    // 1) QKV projection: [8192,1024] @ [1024,3072]
    sgemm_bias_kernel<false><<<dim3(C3/128, NROWS/128), 256>>>(
        x, w_qkv, b_qkv, qkv, NROWS, C3, CEMB);

    // 2) causal attention
    flash_attn_kernel<<<dim3(TSEQ/64, BATCH*NHEAD), 256, ATT_SMEM>>>(qkv, att);

    // 3) xn = LN1(x + att)
    add_ln_kernel<<<NROWS, 256>>>(x, att, ln1_g, ln1_b, xn);

    // 4) h = gelu(xn @ w_fc1 + b_fc1) : [8192,1024] @ [1024,4096]
    sgemm_bias_kernel<true><<<dim3(CFF/128, NROWS/128), 256>>>(
        xn, w_fc1, b_fc1, hbuf, NROWS, CFF, CEMB);

    // 5) mlp = h @ w_fc2 + b_fc2 : [8192,4096] @ [4096,1024]
    sgemm_bias_kernel<false><<<dim3(CEMB/128, NROWS/128), 256>>>(
        hbuf, w_fc2, b_fc2, mlp, NROWS, CEMB, CFF);

    // 6) out = LN2(xn + mlp)
    add_ln_kernel<<<NROWS, 256>>>(xn, mlp, ln2_g, ln2_b, out);
}

// round 5
// speedup vs baseline: 1.5244x; 1.5244x over previous
#include <cuda_runtime.h>
#include <cuda_fp16.h>
#include <math.h>
#include <cstdint>

// ---------------------------------------------------------------------------
// Problem constants
// ---------------------------------------------------------------------------
#define BATCH   4
#define TSEQ    2048
#define CEMB    1024
#define NHEAD   16
#define HDIM    64
#define C3      (3*CEMB)      // 3072
#define CFF     (4*CEMB)      // 4096
#define NROWS   (BATCH*TSEQ)  // 8192
#define LN_EPS  1e-5f

// ---------------------------------------------------------------------------
// Scratch (__device__ globals; alloc-free rule)
// ---------------------------------------------------------------------------
__device__ float  g_qkv[(size_t)NROWS * C3];     // 100 MB  fp32 (attention input)
__device__ float  g_att[(size_t)NROWS * CEMB];   // 33.5 MB
__device__ float  g_xn [(size_t)NROWS * CEMB];   // 33.5 MB
__device__ float  g_mlp[(size_t)NROWS * CEMB];   // 33.5 MB
__device__ __half g_xh [(size_t)NROWS * CEMB];   // 16.8 MB  x in half
__device__ __half g_xnh[(size_t)NROWS * CEMB];   // 16.8 MB  xn in half
__device__ __half g_hh [(size_t)NROWS * CFF];    // 67 MB    gelu(fc1) in half
__device__ __half g_wTq[(size_t)C3  * CEMB];     // 6.3 MB   [3072,1024] half
__device__ __half g_wT1[(size_t)CFF * CEMB];     // 8.4 MB
__device__ __half g_wT2[(size_t)CEMB * CFF];     // 8.4 MB

// ---------------------------------------------------------------------------
// Helpers
// ---------------------------------------------------------------------------
__device__ __forceinline__ uint32_t smem_u32(const void* p) {
    uint32_t a;
    asm("{ .reg .u64 t; cvta.to.shared.u64 t, %1; cvt.u32.u64 %0, t; }"
        : "=r"(a) : "l"(p));
    return a;
}

// SW128 swizzle on byte offsets (rows are 128 bytes)
#define SWZ(o) ((o) ^ (((o) >> 3) & 0x70))

__device__ __forceinline__ void ldmx4(uint32_t* r, uint32_t addr) {
    asm volatile("ldmatrix.sync.aligned.m8n8.x4.shared.b16 {%0,%1,%2,%3}, [%4];"
                 : "=r"(r[0]), "=r"(r[1]), "=r"(r[2]), "=r"(r[3]) : "r"(addr));
}

__device__ __forceinline__ void mma16816(float* d, const uint32_t* a,
                                         const uint32_t* b) {
    asm volatile(
        "mma.sync.aligned.m16n8k16.row.col.f32.f16.f16.f32 "
        "{%0,%1,%2,%3}, {%4,%5,%6,%7}, {%8,%9}, {%0,%1,%2,%3};"
        : "+f"(d[0]), "+f"(d[1]), "+f"(d[2]), "+f"(d[3])
        : "r"(a[0]), "r"(a[1]), "r"(a[2]), "r"(a[3]), "r"(b[0]), "r"(b[1]));
}

// ---------------------------------------------------------------------------
// HMMA GEMM: C[M,N] = A[M,K]@Bt[N,K]^T + bias (opt GeLU). A,Bt half, C OutT.
// CTA tile 128x128, BK=64 halfs (128B rows), 8 warps each 64x32.
// Double-buffered smem (4x16KB = 64KB), register prefetch.
// ---------------------------------------------------------------------------
#define BK 64
#define TILE_BYTES 16384   // 128 rows x 128 bytes

template<bool GELU, typename OutT>
__global__ __launch_bounds__(256)
void hgemm_kernel(const __half* __restrict__ A, const __half* __restrict__ Bt,
                  const float* __restrict__ bias, OutT* __restrict__ C,
                  int M, int N, int K)
{
    extern __shared__ char sm[];
    const uint32_t sbase = smem_u32(sm);
    // layout: A0 | B0 | A1 | B1
    const uint32_t aoff[2] = {0u, 2u * TILE_BYTES};
    const uint32_t boff[2] = {1u * TILE_BYTES, 3u * TILE_BYTES};

    const int t    = threadIdx.x;
    const int wid  = t >> 5;
    const int lane = t & 31;
    const int wm   = wid & 1;      // 2 warp-rows of 64
    const int wn   = wid >> 1;     // 4 warp-cols of 32
    const int row0 = blockIdx.y * 128;
    const int col0 = blockIdx.x * 128;

    const int KT = K / BK;

    float d[4][4][4];
    #pragma unroll
    for (int mt = 0; mt < 4; mt++)
        #pragma unroll
        for (int nt = 0; nt < 4; nt++)
            #pragma unroll
            for (int rr = 0; rr < 4; rr++)
                d[mt][nt][rr] = 0.f;

    // initial stage: 1024 16B-chunks per tile, 4 per thread
    {
        #pragma unroll
        for (int it = 0; it < 4; it++) {
            const int idx = t + it * 256;
            const int r   = idx >> 3;
            const int ch  = idx & 7;
            const uint32_t so = SWZ((uint32_t)(r * 128 + ch * 16));
            *(float4*)(sm + aoff[0] + so) =
                *(const float4*)(A + (size_t)(row0 + r) * K + ch * 8);
            *(float4*)(sm + boff[0] + so) =
                *(const float4*)(Bt + (size_t)(col0 + r) * K + ch * 8);
        }
    }
    __syncthreads();

    float4 pa[4], pb[4];

    for (int kt = 0; kt < KT; kt++) {
        const int buf = kt & 1;
        const bool more = (kt + 1 < KT);

        if (more) {
            const int kk = (kt + 1) * BK;
            #pragma unroll
            for (int it = 0; it < 4; it++) {
                const int idx = t + it * 256;
                const int r   = idx >> 3;
                const int ch  = idx & 7;
                pa[it] = *(const float4*)(A  + (size_t)(row0 + r) * K + kk + ch*8);
                pb[it] = *(const float4*)(Bt + (size_t)(col0 + r) * K + kk + ch*8);
            }
        }

        const uint32_t sa = sbase + aoff[buf];
        const uint32_t sb = sbase + boff[buf];

        #pragma unroll
        for (int kc = 0; kc < 4; kc++) {      // 4 x k16 per buffer
            uint32_t afr[4][4];
            #pragma unroll
            for (int mt = 0; mt < 4; mt++) {
                const int arow = wm * 64 + mt * 16 + (lane & 15);
                const int ach  = kc * 2 + (lane >> 4);
                ldmx4(afr[mt], sa + SWZ((uint32_t)(arow * 128 + ach * 16)));
            }
            uint32_t bfr[2][4];
            #pragma unroll
            for (int nt2 = 0; nt2 < 2; nt2++) {
                const int brow = wn * 32 + nt2 * 16 + ((lane >> 4) << 3) + (lane & 7);
                const int bch  = kc * 2 + ((lane >> 3) & 1);
                ldmx4(bfr[nt2], sb + SWZ((uint32_t)(brow * 128 + bch * 16)));
            }
            #pragma unroll
            for (int mt = 0; mt < 4; mt++)
                #pragma unroll
                for (int nt = 0; nt < 4; nt++)
                    mma16816(d[mt][nt], afr[mt], &bfr[nt >> 1][(nt & 1) * 2]);
        }

        if (more) {
            __syncthreads();
            const int nb = buf ^ 1;
            #pragma unroll
            for (int it = 0; it < 4; it++) {
                const int idx = t + it * 256;
                const int r   = idx >> 3;
                const int ch  = idx & 7;
                const uint32_t so = SWZ((uint32_t)(r * 128 + ch * 16));
                *(float4*)(sm + aoff[nb] + so) = pa[it];
                *(float4*)(sm + boff[nb] + so) = pb[it];
            }
            __syncthreads();
        }
    }

    // epilogue: d0=(r,c) d1=(r,c+1) d2=(r+8,c) d3=(r+8,c+1); r=lane/4, c=(lane%4)*2
    const int er = lane >> 2;
    const int ec = (lane & 3) * 2;
    #pragma unroll
    for (int mt = 0; mt < 4; mt++) {
        #pragma unroll
        for (int nt = 0; nt < 4; nt++) {
            const int col = col0 + wn * 32 + nt * 8 + ec;
            const float b0 = bias[col], b1 = bias[col + 1];
            #pragma unroll
            for (int hf = 0; hf < 2; hf++) {
                const int row = row0 + wm * 64 + mt * 16 + er + hf * 8;
                float v0 = d[mt][nt][hf * 2 + 0] + b0;
                float v1 = d[mt][nt][hf * 2 + 1] + b1;
                if (GELU) {
                    v0 = 0.5f * v0 * (1.f + erff(v0 * 0.70710678118654752f));
                    v1 = 0.5f * v1 * (1.f + erff(v1 * 0.70710678118654752f));
                }
                OutT* dst = C + (size_t)row * N + col;
                if (sizeof(OutT) == 4) {
                    *(float2*)dst = make_float2(v0, v1);
                } else {
                    *(__half2*)dst = __floats2half2_rn(v0, v1);
                }
            }
        }
    }
}

// ---------------------------------------------------------------------------
// fp32 -> fp16 convert
// ---------------------------------------------------------------------------
__global__ __launch_bounds__(256)
void f2h_kernel(const float* __restrict__ in, __half* __restrict__ out, int n4)
{
    const int i = blockIdx.x * 256 + threadIdx.x;
    if (i < n4) {
        float4 v = ((const float4*)in)[i];
        ((__half2*)out)[2*i]   = __floats2half2_rn(v.x, v.y);
        ((__half2*)out)[2*i+1] = __floats2half2_rn(v.z, v.w);
    }
}

// ---------------------------------------------------------------------------
// Weight transpose + convert: out_h[n][k] = (half) in[k][n]
// ---------------------------------------------------------------------------
__global__ __launch_bounds__(256)
void transpose_h_kernel(const float* __restrict__ in, __half* __restrict__ out,
                        int R, int Ccols)   // in is [R][Ccols]
{
    __shared__ float tile[32][33];
    const int c = blockIdx.x * 32 + threadIdx.x;
    const int r = blockIdx.y * 32 + threadIdx.y;
    #pragma unroll
    for (int i = 0; i < 32; i += 8)
        tile[threadIdx.y + i][threadIdx.x] = in[(size_t)(r + i) * Ccols + c];
    __syncthreads();
    const int oc   = blockIdx.y * 32 + threadIdx.x;  // out col = orig row (K)
    const int orow = blockIdx.x * 32 + threadIdx.y;  // out row = orig col (N)
    #pragma unroll
    for (int i = 0; i < 32; i += 8)
        out[(size_t)(orow + i) * R + oc] = __float2half(tile[threadIdx.x][threadIdx.y + i]);
}

// ---------------------------------------------------------------------------
// Flash attention (causal), fp32 — unchanged from passing round-2 kernel
// ---------------------------------------------------------------------------
#define ATT_P 68
#define ATT_SMEM (4 * 64 * ATT_P * 4)

__global__ __launch_bounds__(256)
void flash_attn_kernel(const float* __restrict__ qkv, float* __restrict__ y)
{
    extern __shared__ float smf[];
    float* Qs = smf;
    float* Ks = smf + 64*ATT_P;
    float* Vs = smf + 128*ATT_P;
    float* Ss = smf + 192*ATT_P;

    const int qt = blockIdx.x;
    const int bh = blockIdx.y;
    const int b  = bh >> 4;
    const int h  = bh & 15;
    const int t  = threadIdx.x;
    const int i  = t >> 2;
    const int cg = t & 3;
    const int c0 = cg << 4;
    const int qs = qt * 64;

    const size_t base = (size_t)(b * TSEQ) * C3 + h * HDIM;

    {
        const int d4 = (t & 15) * 4;
        const int r0 = t >> 4;
        #pragma unroll
        for (int rr = 0; rr < 64; rr += 16) {
            int row = r0 + rr;
            *(float4*)&Qs[row*ATT_P + d4] =
                *(const float4*)(qkv + base + (size_t)(qs + row) * C3 + d4);
        }
    }

    float m = -INFINITY, l = 0.f;
    float O[16];
    #pragma unroll
    for (int j = 0; j < 16; j++) O[j] = 0.f;

    for (int kt = 0; kt <= qt; kt++) {
        const int ks = kt * 64;
        __syncthreads();
        {
            const int d4 = (t & 15) * 4;
            const int r0 = t >> 4;
            #pragma unroll
            for (int rr = 0; rr < 64; rr += 16) {
                int row = r0 + rr;
                const float* kp = qkv + base + (size_t)(ks + row) * C3 + CEMB + d4;
                *(float4*)&Ks[row*ATT_P + d4] = *(const float4*)kp;
                *(float4*)&Vs[row*ATT_P + d4] = *(const float4*)(kp + CEMB);
            }
        }
        __syncthreads();

        float acc[16];
        #pragma unroll
        for (int jj = 0; jj < 16; jj++) acc[jj] = 0.f;
        #pragma unroll 4
        for (int d4 = 0; d4 < 64; d4 += 4) {
            float4 qv = *(const float4*)&Qs[i*ATT_P + d4];
            #pragma unroll
            for (int jj = 0; jj < 16; jj++) {
                float4 kv = *(const float4*)&Ks[(c0+jj)*ATT_P + d4];
                acc[jj] += qv.x*kv.x + qv.y*kv.y + qv.z*kv.z + qv.w*kv.w;
            }
        }

        const bool diag = (kt == qt);
        float mt = -INFINITY;
        #pragma unroll
        for (int jj = 0; jj < 16; jj++) {
            float s = acc[jj] * 0.125f;
            if (diag && (c0 + jj) > i) s = -INFINITY;
            acc[jj] = s;
            mt = fmaxf(mt, s);
        }
        mt = fmaxf(mt, __shfl_xor_sync(0xffffffffu, mt, 1));
        mt = fmaxf(mt, __shfl_xor_sync(0xffffffffu, mt, 2));
        const float mnew = fmaxf(m, mt);

        float lt = 0.f;
        #pragma unroll
        for (int jj = 0; jj < 16; jj++) {
            float p = expf(acc[jj] - mnew);
            Ss[i*ATT_P + c0 + jj] = p;
            lt += p;
        }
        lt += __shfl_xor_sync(0xffffffffu, lt, 1);
        lt += __shfl_xor_sync(0xffffffffu, lt, 2);

        const float scale = expf(m - mnew);
        m = mnew;
        l = l * scale + lt;
        #pragma unroll
        for (int cc = 0; cc < 16; cc++) O[cc] *= scale;
        __syncthreads();

        for (int j = 0; j < 64; j++) {
            float p = Ss[i*ATT_P + j];
            const float* vrow = &Vs[j*ATT_P + c0];
            #pragma unroll
            for (int cc4 = 0; cc4 < 16; cc4 += 4) {
                float4 vv = *(const float4*)(vrow + cc4);
                O[cc4+0] = fmaf(p, vv.x, O[cc4+0]);
                O[cc4+1] = fmaf(p, vv.y, O[cc4+1]);
                O[cc4+2] = fmaf(p, vv.z, O[cc4+2]);
                O[cc4+3] = fmaf(p, vv.w, O[cc4+3]);
            }
        }
    }

    const float inv = 1.f / l;
    float* dst = y + (size_t)(b * TSEQ + qs + i) * CEMB + h * HDIM + c0;
    #pragma unroll
    for (int cc = 0; cc < 16; cc++) dst[cc] = O[cc] * inv;
}

// ---------------------------------------------------------------------------
// Fused residual-add + LayerNorm; also writes half copy for next GEMM
// ---------------------------------------------------------------------------
__global__ __launch_bounds__(256)
void add_ln_kernel(const float* __restrict__ a, const float* __restrict__ r,
                   const float* __restrict__ gam, const float* __restrict__ bet,
                   float* __restrict__ out, __half* __restrict__ outh)
{
    const int row = blockIdx.x;
    const int t   = threadIdx.x;

    float4 va = ((const float4*)(a + (size_t)row * CEMB))[t];
    float4 vr = ((const float4*)(r + (size_t)row * CEMB))[t];
    float4 v;
    v.x = va.x + vr.x; v.y = va.y + vr.y; v.z = va.z + vr.z; v.w = va.w + vr.w;

    float s  = v.x + v.y + v.z + v.w;
    float sq = v.x*v.x + v.y*v.y + v.z*v.z + v.w*v.w;
    #pragma unroll
    for (int o = 16; o; o >>= 1) {
        s  += __shfl_xor_sync(0xffffffffu, s,  o);
        sq += __shfl_xor_sync(0xffffffffu, sq, o);
    }
    __shared__ float ps[8], pq[8];
    const int w = t >> 5, lane = t & 31;
    if (lane == 0) { ps[w] = s; pq[w] = sq; }
    __syncthreads();
    s = 0.f; sq = 0.f;
    #pragma unroll
    for (int k = 0; k < 8; k++) { s += ps[k]; sq += pq[k]; }

    const float mu   = s * (1.f / CEMB);
    const float var  = sq * (1.f / CEMB) - mu * mu;
    const float rstd = rsqrtf(var + LN_EPS);

    float4 gg = ((const float4*)gam)[t];
    float4 bb = ((const float4*)bet)[t];
    float4 o;
    o.x = (v.x - mu) * rstd * gg.x + bb.x;
    o.y = (v.y - mu) * rstd * gg.y + bb.y;
    o.z = (v.z - mu) * rstd * gg.z + bb.z;
    o.w = (v.w - mu) * rstd * gg.w + bb.w;
    ((float4*)(out + (size_t)row * CEMB))[t] = o;
    __half2* oh = (__half2*)(outh + (size_t)row * CEMB);
    oh[2*t]   = __floats2half2_rn(o.x, o.y);
    oh[2*t+1] = __floats2half2_rn(o.z, o.w);
}

// ---------------------------------------------------------------------------
// Launch
// ---------------------------------------------------------------------------
#define GT_SMEM (4 * TILE_BYTES)   // 65536

extern "C" void kernel_launch(void* const* d_in, const int* in_sizes, int n_in,
                              void* d_out, int out_size)
{
    const float* x     = (const float*)d_in[0];
    const float* w_qkv = (const float*)d_in[1];
    const float* b_qkv = (const float*)d_in[2];
    const float* ln1_g = (const float*)d_in[3];
    const float* ln1_b = (const float*)d_in[4];
    const float* w_fc1 = (const float*)d_in[5];
    const float* b_fc1 = (const float*)d_in[6];
    const float* w_fc2 = (const float*)d_in[7];
    const float* b_fc2 = (const float*)d_in[8];
    const float* ln2_g = (const float*)d_in[9];
    const float* ln2_b = (const float*)d_in[10];
    float* out = (float*)d_out;

    void *p_qkv, *p_att, *p_xn, *p_mlp, *p_xh, *p_xnh, *p_hh, *p_wq, *p_w1, *p_w2;
    cudaGetSymbolAddress(&p_qkv, g_qkv);
    cudaGetSymbolAddress(&p_att, g_att);
    cudaGetSymbolAddress(&p_xn,  g_xn);
    cudaGetSymbolAddress(&p_mlp, g_mlp);
    cudaGetSymbolAddress(&p_xh,  g_xh);
    cudaGetSymbolAddress(&p_xnh, g_xnh);
    cudaGetSymbolAddress(&p_hh,  g_hh);
    cudaGetSymbolAddress(&p_wq,  g_wTq);
    cudaGetSymbolAddress(&p_w1,  g_wT1);
    cudaGetSymbolAddress(&p_w2,  g_wT2);
    float*  qkv  = (float*)p_qkv;
    float*  att  = (float*)p_att;
    float*  xn   = (float*)p_xn;
    float*  mlp  = (float*)p_mlp;
    __half* xh   = (__half*)p_xh;
    __half* xnh  = (__half*)p_xnh;
    __half* hh   = (__half*)p_hh;
    __half* wTq  = (__half*)p_wq;
    __half* wT1  = (__half*)p_w1;
    __half* wT2  = (__half*)p_w2;

    cudaFuncSetAttribute(flash_attn_kernel,
                         cudaFuncAttributeMaxDynamicSharedMemorySize, ATT_SMEM);
    cudaFuncSetAttribute((const void*)hgemm_kernel<false, float>,
                         cudaFuncAttributeMaxDynamicSharedMemorySize, GT_SMEM);
    cudaFuncSetAttribute((const void*)hgemm_kernel<true, __half>,
                         cudaFuncAttributeMaxDynamicSharedMemorySize, GT_SMEM);

    // 0) conversions
    f2h_kernel<<<(NROWS*CEMB/4 + 255)/256, 256>>>(x, xh, NROWS*CEMB/4);
    transpose_h_kernel<<<dim3(C3/32,  CEMB/32), dim3(32,8)>>>(w_qkv, wTq, CEMB, C3);
    transpose_h_kernel<<<dim3(CFF/32, CEMB/32), dim3(32,8)>>>(w_fc1, wT1, CEMB, CFF);
    transpose_h_kernel<<<dim3(CEMB/32, CFF/32), dim3(32,8)>>>(w_fc2, wT2, CFF, CEMB);

    // 1) QKV projection (fp32 out)
    hgemm_kernel<false, float><<<dim3(C3/128, NROWS/128), 256, GT_SMEM>>>(
        xh, wTq, b_qkv, qkv, NROWS, C3, CEMB);

    // 2) causal attention (fp32)
    flash_attn_kernel<<<dim3(TSEQ/64, BATCH*NHEAD), 256, ATT_SMEM>>>(qkv, att);

    // 3) xn = LN1(x + att) (+ half copy)
    add_ln_kernel<<<NROWS, 256>>>(x, att, ln1_g, ln1_b, xn, xnh);

    // 4) h = gelu(xn @ w_fc1 + b_fc1) (half out)
    hgemm_kernel<true, __half><<<dim3(CFF/128, NROWS/128), 256, GT_SMEM>>>(
        xnh, wT1, b_fc1, hh, NROWS, CFF, CEMB);

    // 5) mlp = h @ w_fc2 + b_fc2 (fp32 out)
    hgemm_kernel<false, float><<<dim3(CEMB/128, NROWS/128), 256, GT_SMEM>>>(
        hh, wT2, b_fc2, mlp, NROWS, CEMB, CFF);

    // 6) out = LN2(xn + mlp)  (half copy to dead buffer)
    add_ln_kernel<<<NROWS, 256>>>(xn, mlp, ln2_g, ln2_b, out, xnh);
}

// round 6
// speedup vs baseline: 1.5772x; 1.0347x over previous
#include <cuda_runtime.h>
#include <cuda_fp16.h>
#include <math.h>
#include <cstdint>

// ---------------------------------------------------------------------------
// Problem constants
// ---------------------------------------------------------------------------
#define BATCH   4
#define TSEQ    2048
#define CEMB    1024
#define NHEAD   16
#define HDIM    64
#define C3      (3*CEMB)      // 3072
#define CFF     (4*CEMB)      // 4096
#define NROWS   (BATCH*TSEQ)  // 8192
#define LN_EPS  1e-5f

// ---------------------------------------------------------------------------
// Scratch (__device__ globals; alloc-free rule)
// ---------------------------------------------------------------------------
__device__ float  g_qkv[(size_t)NROWS * C3];     // fp32 (attention input)
__device__ float  g_att[(size_t)NROWS * CEMB];
__device__ float  g_xn [(size_t)NROWS * CEMB];
__device__ float  g_mlp[(size_t)NROWS * CEMB];
__device__ __half g_xh [(size_t)NROWS * CEMB];   // x in half
__device__ __half g_xnh[(size_t)NROWS * CEMB];   // xn in half
__device__ __half g_hh [(size_t)NROWS * CFF];    // gelu(fc1) in half
__device__ __half g_wTq[(size_t)C3  * CEMB];     // [3072,1024] half (K-major)
__device__ __half g_wT1[(size_t)CFF * CEMB];
__device__ __half g_wT2[(size_t)CEMB * CFF];

// ---------------------------------------------------------------------------
// Helpers
// ---------------------------------------------------------------------------
__device__ __forceinline__ uint32_t smem_u32(const void* p) {
    uint32_t a;
    asm("{ .reg .u64 t; cvta.to.shared.u64 t, %1; cvt.u32.u64 %0, t; }"
        : "=r"(a) : "l"(p));
    return a;
}

// SW128 swizzle on byte offsets (rows are 128 bytes)
#define SWZ(o) ((o) ^ (((o) >> 3) & 0x70))

__device__ __forceinline__ void ldmx4(uint32_t* r, uint32_t addr) {
    asm volatile("ldmatrix.sync.aligned.m8n8.x4.shared.b16 {%0,%1,%2,%3}, [%4];"
                 : "=r"(r[0]), "=r"(r[1]), "=r"(r[2]), "=r"(r[3]) : "r"(addr));
}

__device__ __forceinline__ void mma16816(float* d, const uint32_t* a,
                                         const uint32_t* b) {
    asm volatile(
        "mma.sync.aligned.m16n8k16.row.col.f32.f16.f16.f32 "
        "{%0,%1,%2,%3}, {%4,%5,%6,%7}, {%8,%9}, {%0,%1,%2,%3};"
        : "+f"(d[0]), "+f"(d[1]), "+f"(d[2]), "+f"(d[3])
        : "r"(a[0]), "r"(a[1]), "r"(a[2]), "r"(a[3]), "r"(b[0]), "r"(b[1]));
}

__device__ __forceinline__ void cpasync16(uint32_t s, const void* g) {
    asm volatile("cp.async.cg.shared.global [%0], [%1], 16;" :: "r"(s), "l"(g));
}
__device__ __forceinline__ void cpasync_commit() {
    asm volatile("cp.async.commit_group;" ::: "memory");
}
template<int N>
__device__ __forceinline__ void cpasync_wait() {
    asm volatile("cp.async.wait_group %0;" :: "n"(N) : "memory");
}

// ---------------------------------------------------------------------------
// HMMA GEMM: C[M,N] = A[M,K]@Bt[N,K]^T + bias (opt GeLU). A,Bt half, C OutT.
// CTA tile 128x128, BK=64 halfs (128B rows), 8 warps each 64x32.
// cp.async 3-stage pipeline (96KB smem), 2 CTAs/SM.
// ---------------------------------------------------------------------------
#define BK 64
#define TILE_BYTES 16384       // 128 rows x 128 bytes
#define STAGE_BYTES 32768      // A tile + B tile
#define NSTAGE 3
#define GT_SMEM (NSTAGE * STAGE_BYTES)   // 98304

template<bool GELU, typename OutT>
__global__ __launch_bounds__(256, 2)
void hgemm_kernel(const __half* __restrict__ A, const __half* __restrict__ Bt,
                  const float* __restrict__ bias, OutT* __restrict__ C,
                  int M, int N, int K)
{
    extern __shared__ char sm[];
    const uint32_t sbase = smem_u32(sm);

    const int t    = threadIdx.x;
    const int wid  = t >> 5;
    const int lane = t & 31;
    const int wm   = wid & 1;      // 2 warp-rows of 64
    const int wn   = wid >> 1;     // 4 warp-cols of 32
    const int row0 = blockIdx.y * 128;
    const int col0 = blockIdx.x * 128;

    const int KT = K / BK;

    // per-thread staging coords (4 chunks per operand per stage)
    const int srow[4] = { (t + 0)   >> 3, (t + 256) >> 3,
                          (t + 512) >> 3, (t + 768) >> 3 };
    const int sch = t & 7;
    const uint32_t sso[4] = {
        SWZ((uint32_t)(srow[0] * 128 + sch * 16)),
        SWZ((uint32_t)(srow[1] * 128 + sch * 16)),
        SWZ((uint32_t)(srow[2] * 128 + sch * 16)),
        SWZ((uint32_t)(srow[3] * 128 + sch * 16)) };

    // issue one stage of loads for K-tile kt into stage slot st
    #define ISSUE(kt, st)                                                      \
        {                                                                      \
            const int kk_ = (kt) * BK;                                         \
            const uint32_t ab = sbase + (uint32_t)(st) * STAGE_BYTES;          \
            const uint32_t bb = ab + TILE_BYTES;                               \
            _Pragma("unroll")                                                  \
            for (int it = 0; it < 4; it++) {                                   \
                cpasync16(ab + sso[it],                                        \
                          A  + (size_t)(row0 + srow[it]) * K + kk_ + sch * 8); \
                cpasync16(bb + sso[it],                                        \
                          Bt + (size_t)(col0 + srow[it]) * K + kk_ + sch * 8); \
            }                                                                  \
        }

    float d[4][4][4];
    #pragma unroll
    for (int mt = 0; mt < 4; mt++)
        #pragma unroll
        for (int nt = 0; nt < 4; nt++)
            #pragma unroll
            for (int rr = 0; rr < 4; rr++)
                d[mt][nt][rr] = 0.f;

    // prologue: stages 0,1
    ISSUE(0, 0); cpasync_commit();
    ISSUE(1, 1); cpasync_commit();

    int st = 0;
    for (int kt = 0; kt < KT; kt++) {
        cpasync_wait<1>();       // stage kt resident
        __syncthreads();

        const uint32_t sa = sbase + (uint32_t)st * STAGE_BYTES;
        const uint32_t sb = sa + TILE_BYTES;

        #pragma unroll
        for (int kc = 0; kc < 4; kc++) {      // 4 x k16 per stage
            uint32_t afr[4][4];
            #pragma unroll
            for (int mt = 0; mt < 4; mt++) {
                const int arow = wm * 64 + mt * 16 + (lane & 15);
                const int ach  = kc * 2 + (lane >> 4);
                ldmx4(afr[mt], sa + SWZ((uint32_t)(arow * 128 + ach * 16)));
            }
            uint32_t bfr[2][4];
            #pragma unroll
            for (int nt2 = 0; nt2 < 2; nt2++) {
                const int brow = wn * 32 + nt2 * 16 + ((lane >> 4) << 3) + (lane & 7);
                const int bch  = kc * 2 + ((lane >> 3) & 1);
                ldmx4(bfr[nt2], sb + SWZ((uint32_t)(brow * 128 + bch * 16)));
            }
            #pragma unroll
            for (int mt = 0; mt < 4; mt++)
                #pragma unroll
                for (int nt = 0; nt < 4; nt++)
                    mma16816(d[mt][nt], afr[mt], &bfr[nt >> 1][(nt & 1) * 2]);
        }

        // issue stage kt+2 into the slot freed at iteration kt-1
        const int nst = (st + 2 >= NSTAGE) ? st + 2 - NSTAGE : st + 2;
        if (kt + 2 < KT) ISSUE(kt + 2, nst);
        cpasync_commit();
        st = (st + 1 == NSTAGE) ? 0 : st + 1;
    }

    // epilogue: d0=(r,c) d1=(r,c+1) d2=(r+8,c) d3=(r+8,c+1); r=lane/4, c=(lane%4)*2
    const int er = lane >> 2;
    const int ec = (lane & 3) * 2;
    #pragma unroll
    for (int mt = 0; mt < 4; mt++) {
        #pragma unroll
        for (int nt = 0; nt < 4; nt++) {
            const int col = col0 + wn * 32 + nt * 8 + ec;
            const float b0 = bias[col], b1 = bias[col + 1];
            #pragma unroll
            for (int hf = 0; hf < 2; hf++) {
                const int row = row0 + wm * 64 + mt * 16 + er + hf * 8;
                float v0 = d[mt][nt][hf * 2 + 0] + b0;
                float v1 = d[mt][nt][hf * 2 + 1] + b1;
                if (GELU) {
                    v0 = 0.5f * v0 * (1.f + erff(v0 * 0.70710678118654752f));
                    v1 = 0.5f * v1 * (1.f + erff(v1 * 0.70710678118654752f));
                }
                OutT* dst = C + (size_t)row * N + col;
                if (sizeof(OutT) == 4) {
                    *(float2*)dst = make_float2(v0, v1);
                } else {
                    *(__half2*)dst = __floats2half2_rn(v0, v1);
                }
            }
        }
    }
    #undef ISSUE
}

// ---------------------------------------------------------------------------
// fp32 -> fp16 convert
// ---------------------------------------------------------------------------
__global__ __launch_bounds__(256)
void f2h_kernel(const float* __restrict__ in, __half* __restrict__ out, int n4)
{
    const int i = blockIdx.x * 256 + threadIdx.x;
    if (i < n4) {
        float4 v = ((const float4*)in)[i];
        ((__half2*)out)[2*i]   = __floats2half2_rn(v.x, v.y);
        ((__half2*)out)[2*i+1] = __floats2half2_rn(v.z, v.w);
    }
}

// ---------------------------------------------------------------------------
// Weight transpose + convert: out_h[n][k] = (half) in[k][n]
// ---------------------------------------------------------------------------
__global__ __launch_bounds__(256)
void transpose_h_kernel(const float* __restrict__ in, __half* __restrict__ out,
                        int R, int Ccols)   // in is [R][Ccols]
{
    __shared__ float tile[32][33];
    const int c = blockIdx.x * 32 + threadIdx.x;
    const int r = blockIdx.y * 32 + threadIdx.y;
    #pragma unroll
    for (int i = 0; i < 32; i += 8)
        tile[threadIdx.y + i][threadIdx.x] = in[(size_t)(r + i) * Ccols + c];
    __syncthreads();
    const int oc   = blockIdx.y * 32 + threadIdx.x;  // out col = orig row (K)
    const int orow = blockIdx.x * 32 + threadIdx.y;  // out row = orig col (N)
    #pragma unroll
    for (int i = 0; i < 32; i += 8)
        out[(size_t)(orow + i) * R + oc] = __float2half(tile[threadIdx.x][threadIdx.y + i]);
}

// ---------------------------------------------------------------------------
// Flash attention (causal), fp32
// ---------------------------------------------------------------------------
#define ATT_P 68
#define ATT_SMEM (4 * 64 * ATT_P * 4)

__global__ __launch_bounds__(256)
void flash_attn_kernel(const float* __restrict__ qkv, float* __restrict__ y)
{
    extern __shared__ float smf[];
    float* Qs = smf;
    float* Ks = smf + 64*ATT_P;
    float* Vs = smf + 128*ATT_P;
    float* Ss = smf + 192*ATT_P;

    const int qt = blockIdx.x;
    const int bh = blockIdx.y;
    const int b  = bh >> 4;
    const int h  = bh & 15;
    const int t  = threadIdx.x;
    const int i  = t >> 2;
    const int cg = t & 3;
    const int c0 = cg << 4;
    const int qs = qt * 64;

    const size_t base = (size_t)(b * TSEQ) * C3 + h * HDIM;

    {
        const int d4 = (t & 15) * 4;
        const int r0 = t >> 4;
        #pragma unroll
        for (int rr = 0; rr < 64; rr += 16) {
            int row = r0 + rr;
            *(float4*)&Qs[row*ATT_P + d4] =
                *(const float4*)(qkv + base + (size_t)(qs + row) * C3 + d4);
        }
    }

    float m = -INFINITY, l = 0.f;
    float O[16];
    #pragma unroll
    for (int j = 0; j < 16; j++) O[j] = 0.f;

    for (int kt = 0; kt <= qt; kt++) {
        const int ks = kt * 64;
        __syncthreads();
        {
            const int d4 = (t & 15) * 4;
            const int r0 = t >> 4;
            #pragma unroll
            for (int rr = 0; rr < 64; rr += 16) {
                int row = r0 + rr;
                const float* kp = qkv + base + (size_t)(ks + row) * C3 + CEMB + d4;
                *(float4*)&Ks[row*ATT_P + d4] = *(const float4*)kp;
                *(float4*)&Vs[row*ATT_P + d4] = *(const float4*)(kp + CEMB);
            }
        }
        __syncthreads();

        float acc[16];
        #pragma unroll
        for (int jj = 0; jj < 16; jj++) acc[jj] = 0.f;
        #pragma unroll 4
        for (int d4 = 0; d4 < 64; d4 += 4) {
            float4 qv = *(const float4*)&Qs[i*ATT_P + d4];
            #pragma unroll
            for (int jj = 0; jj < 16; jj++) {
                float4 kv = *(const float4*)&Ks[(c0+jj)*ATT_P + d4];
                acc[jj] += qv.x*kv.x + qv.y*kv.y + qv.z*kv.z + qv.w*kv.w;
            }
        }

        const bool diag = (kt == qt);
        float mt = -INFINITY;
        #pragma unroll
        for (int jj = 0; jj < 16; jj++) {
            float s = acc[jj] * 0.125f;
            if (diag && (c0 + jj) > i) s = -INFINITY;
            acc[jj] = s;
            mt = fmaxf(mt, s);
        }
        mt = fmaxf(mt, __shfl_xor_sync(0xffffffffu, mt, 1));
        mt = fmaxf(mt, __shfl_xor_sync(0xffffffffu, mt, 2));
        const float mnew = fmaxf(m, mt);

        float lt = 0.f;
        #pragma unroll
        for (int jj = 0; jj < 16; jj++) {
            float p = __expf(acc[jj] - mnew);
            Ss[i*ATT_P + c0 + jj] = p;
            lt += p;
        }
        lt += __shfl_xor_sync(0xffffffffu, lt, 1);
        lt += __shfl_xor_sync(0xffffffffu, lt, 2);

        const float scale = __expf(m - mnew);
        m = mnew;
        l = l * scale + lt;
        #pragma unroll
        for (int cc = 0; cc < 16; cc++) O[cc] *= scale;
        __syncthreads();

        for (int j = 0; j < 64; j++) {
            float p = Ss[i*ATT_P + j];
            const float* vrow = &Vs[j*ATT_P + c0];
            #pragma unroll
            for (int cc4 = 0; cc4 < 16; cc4 += 4) {
                float4 vv = *(const float4*)(vrow + cc4);
                O[cc4+0] = fmaf(p, vv.x, O[cc4+0]);
                O[cc4+1] = fmaf(p, vv.y, O[cc4+1]);
                O[cc4+2] = fmaf(p, vv.z, O[cc4+2]);
                O[cc4+3] = fmaf(p, vv.w, O[cc4+3]);
            }
        }
    }

    const float inv = 1.f / l;
    float* dst = y + (size_t)(b * TSEQ + qs + i) * CEMB + h * HDIM + c0;
    #pragma unroll
    for (int cc = 0; cc < 16; cc++) dst[cc] = O[cc] * inv;
}

// ---------------------------------------------------------------------------
// Fused residual-add + LayerNorm; also writes half copy for next GEMM
// ---------------------------------------------------------------------------
__global__ __launch_bounds__(256)
void add_ln_kernel(const float* __restrict__ a, const float* __restrict__ r,
                   const float* __restrict__ gam, const float* __restrict__ bet,
                   float* __restrict__ out, __half* __restrict__ outh)
{
    const int row = blockIdx.x;
    const int t   = threadIdx.x;

    float4 va = ((const float4*)(a + (size_t)row * CEMB))[t];
    float4 vr = ((const float4*)(r + (size_t)row * CEMB))[t];
    float4 v;
    v.x = va.x + vr.x; v.y = va.y + vr.y; v.z = va.z + vr.z; v.w = va.w + vr.w;

    float s  = v.x + v.y + v.z + v.w;
    float sq = v.x*v.x + v.y*v.y + v.z*v.z + v.w*v.w;
    #pragma unroll
    for (int o = 16; o; o >>= 1) {
        s  += __shfl_xor_sync(0xffffffffu, s,  o);
        sq += __shfl_xor_sync(0xffffffffu, sq, o);
    }
    __shared__ float ps[8], pq[8];
    const int w = t >> 5, lane = t & 31;
    if (lane == 0) { ps[w] = s; pq[w] = sq; }
    __syncthreads();
    s = 0.f; sq = 0.f;
    #pragma unroll
    for (int k = 0; k < 8; k++) { s += ps[k]; sq += pq[k]; }

    const float mu   = s * (1.f / CEMB);
    const float var  = sq * (1.f / CEMB) - mu * mu;
    const float rstd = rsqrtf(var + LN_EPS);

    float4 gg = ((const float4*)gam)[t];
    float4 bb = ((const float4*)bet)[t];
    float4 o;
    o.x = (v.x - mu) * rstd * gg.x + bb.x;
    o.y = (v.y - mu) * rstd * gg.y + bb.y;
    o.z = (v.z - mu) * rstd * gg.z + bb.z;
    o.w = (v.w - mu) * rstd * gg.w + bb.w;
    ((float4*)(out + (size_t)row * CEMB))[t] = o;
    __half2* oh = (__half2*)(outh + (size_t)row * CEMB);
    oh[2*t]   = __floats2half2_rn(o.x, o.y);
    oh[2*t+1] = __floats2half2_rn(o.z, o.w);
}

// ---------------------------------------------------------------------------
// Launch
// ---------------------------------------------------------------------------
extern "C" void kernel_launch(void* const* d_in, const int* in_sizes, int n_in,
                              void* d_out, int out_size)
{
    const float* x     = (const float*)d_in[0];
    const float* w_qkv = (const float*)d_in[1];
    const float* b_qkv = (const float*)d_in[2];
    const float* ln1_g = (const float*)d_in[3];
    const float* ln1_b = (const float*)d_in[4];
    const float* w_fc1 = (const float*)d_in[5];
    const float* b_fc1 = (const float*)d_in[6];
    const float* w_fc2 = (const float*)d_in[7];
    const float* b_fc2 = (const float*)d_in[8];
    const float* ln2_g = (const float*)d_in[9];
    const float* ln2_b = (const float*)d_in[10];
    float* out = (float*)d_out;

    void *p_qkv, *p_att, *p_xn, *p_mlp, *p_xh, *p_xnh, *p_hh, *p_wq, *p_w1, *p_w2;
    cudaGetSymbolAddress(&p_qkv, g_qkv);
    cudaGetSymbolAddress(&p_att, g_att);
    cudaGetSymbolAddress(&p_xn,  g_xn);
    cudaGetSymbolAddress(&p_mlp, g_mlp);
    cudaGetSymbolAddress(&p_xh,  g_xh);
    cudaGetSymbolAddress(&p_xnh, g_xnh);
    cudaGetSymbolAddress(&p_hh,  g_hh);
    cudaGetSymbolAddress(&p_wq,  g_wTq);
    cudaGetSymbolAddress(&p_w1,  g_wT1);
    cudaGetSymbolAddress(&p_w2,  g_wT2);
    float*  qkv  = (float*)p_qkv;
    float*  att  = (float*)p_att;
    float*  xn   = (float*)p_xn;
    float*  mlp  = (float*)p_mlp;
    __half* xh   = (__half*)p_xh;
    __half* xnh  = (__half*)p_xnh;
    __half* hh   = (__half*)p_hh;
    __half* wTq  = (__half*)p_wq;
    __half* wT1  = (__half*)p_w1;
    __half* wT2  = (__half*)p_w2;

    cudaFuncSetAttribute(flash_attn_kernel,
                         cudaFuncAttributeMaxDynamicSharedMemorySize, ATT_SMEM);
    cudaFuncSetAttribute((const void*)hgemm_kernel<false, float>,
                         cudaFuncAttributeMaxDynamicSharedMemorySize, GT_SMEM);
    cudaFuncSetAttribute((const void*)hgemm_kernel<true, __half>,
                         cudaFuncAttributeMaxDynamicSharedMemorySize, GT_SMEM);

    // 0) conversions
    f2h_kernel<<<(NROWS*CEMB/4 + 255)/256, 256>>>(x, xh, NROWS*CEMB/4);
    transpose_h_kernel<<<dim3(C3/32,  CEMB/32), dim3(32,8)>>>(w_qkv, wTq, CEMB, C3);
    transpose_h_kernel<<<dim3(CFF/32, CEMB/32), dim3(32,8)>>>(w_fc1, wT1, CEMB, CFF);
    transpose_h_kernel<<<dim3(CEMB/32, CFF/32), dim3(32,8)>>>(w_fc2, wT2, CFF, CEMB);

    // 1) QKV projection (fp32 out)
    hgemm_kernel<false, float><<<dim3(C3/128, NROWS/128), 256, GT_SMEM>>>(
        xh, wTq, b_qkv, qkv, NROWS, C3, CEMB);

    // 2) causal attention (fp32)
    flash_attn_kernel<<<dim3(TSEQ/64, BATCH*NHEAD), 256, ATT_SMEM>>>(qkv, att);

    // 3) xn = LN1(x + att) (+ half copy)
    add_ln_kernel<<<NROWS, 256>>>(x, att, ln1_g, ln1_b, xn, xnh);

    // 4) h = gelu(xn @ w_fc1 + b_fc1) (half out)
    hgemm_kernel<true, __half><<<dim3(CFF/128, NROWS/128), 256, GT_SMEM>>>(
        xnh, wT1, b_fc1, hh, NROWS, CFF, CEMB);

    // 5) mlp = h @ w_fc2 + b_fc2 (fp32 out)
    hgemm_kernel<false, float><<<dim3(CEMB/128, NROWS/128), 256, GT_SMEM>>>(
        hh, wT2, b_fc2, mlp, NROWS, CEMB, CFF);

    // 6) out = LN2(xn + mlp)  (half copy to dead buffer)
    add_ln_kernel<<<NROWS, 256>>>(xn, mlp, ln2_g, ln2_b, out, xnh);
}